// round 7
// baseline (speedup 1.0000x reference)
#include <cuda_runtime.h>
#include <math.h>
#include <stdint.h>

// ---------------- static device scratch (no allocation allowed) ----------------
__device__ float    g_xg1 [(size_t)32768 * 1024];   // layer1 input projection, layout [b][t][j*4+g]
__device__ float    g_out1[(size_t)32768 * 256];    // layer1 hidden outputs [b][t][j] (tf32-rounded)
__device__ float    g_w1cv[(size_t)1024 * 2048];    // Wih1 rounded to tf32
__device__ float    g_h2f [64 * 128];               // final layer2 h
__device__ unsigned g_flag1[8];                     // per batch-group step counters

// ---------------- helpers ----------------
__device__ __forceinline__ unsigned f2tf32(float f) {
    unsigned r;
    asm("cvt.rna.tf32.f32 %0, %1;" : "=r"(r) : "f"(f));
    return r;
}

__device__ __forceinline__ void mma_tf32(float* c, const unsigned* a, const unsigned* b) {
    asm volatile(
        "mma.sync.aligned.m16n8k8.row.col.f32.tf32.tf32.f32 "
        "{%0,%1,%2,%3},{%4,%5,%6,%7},{%8,%9},{%0,%1,%2,%3};"
        : "+f"(c[0]), "+f"(c[1]), "+f"(c[2]), "+f"(c[3])
        : "r"(a[0]), "r"(a[1]), "r"(a[2]), "r"(a[3]), "r"(b[0]), "r"(b[1]));
}

__device__ __forceinline__ void cp_async16(void* smem_dst, const void* gptr) {
    unsigned s = (unsigned)__cvta_generic_to_shared(smem_dst);
    asm volatile("cp.async.cg.shared.global [%0], [%1], 16;\n" :: "r"(s), "l"(gptr));
}
#define CP_COMMIT() asm volatile("cp.async.commit_group;\n" ::: "memory")
#define CP_WAIT0()  asm volatile("cp.async.wait_group 0;\n" ::: "memory")

__device__ __forceinline__ uint32_t smem_u32(const void* p) {
    return (uint32_t)__cvta_generic_to_shared(p);
}
__device__ __forceinline__ uint32_t my_ctarank() {
    uint32_t r;
    asm("mov.u32 %0, %%cluster_ctarank;" : "=r"(r));
    return r;
}
#define CLUSTER_ARRIVE() asm volatile("barrier.cluster.arrive.aligned;" ::: "memory")
#define CLUSTER_WAIT()   asm volatile("barrier.cluster.wait.aligned;" ::: "memory")

__device__ __forceinline__ void red_release_gpu_add(unsigned* p) {
    asm volatile("red.release.gpu.global.add.u32 [%0], 1;" :: "l"(p) : "memory");
}
__device__ __forceinline__ unsigned ld_acquire_gpu(const unsigned* p) {
    unsigned v;
    asm volatile("ld.acquire.gpu.global.u32 %0, [%1];" : "=r"(v) : "l"(p) : "memory");
    return v;
}

// fast precise activations (MUFU ex2 + rcp; err ~1e-6)
__device__ __forceinline__ float fsigmoid(float x) {
    return 1.f / (1.f + __expf(-x));
}
__device__ __forceinline__ float ftanh(float x) {
    return 1.f - 2.f / (1.f + __expf(2.f * x));
}

// ---------------- prep: round weights to tf32 once ----------------
__global__ void cvt_rna_kernel(const float* __restrict__ src, float* __restrict__ dst, int n) {
    int i = blockIdx.x * 256 + threadIdx.x;
    if (i < n) dst[i] = __uint_as_float(f2tf32(src[i]));
}

// ---------------- tf32 GEMM with permuted output columns (layer1 input proj) ----------------
__global__ void __launch_bounds__(256, 2) gemm_tf32_perm(
    const float* __restrict__ A, const float* __restrict__ W,
    const float* __restrict__ b1, const float* __restrict__ b2,
    float* __restrict__ C, int M, int N, int K)
{
    extern __shared__ unsigned sh[];
    unsigned* As = sh;                 // [2][128][36]
    unsigned* Bs = sh + 2 * 128 * 36;  // [2][128][36]

    const int tid = threadIdx.x, lane = tid & 31, warp = tid >> 5;
    const int wm = warp & 1, wn = warp >> 1;
    const int g = lane >> 2, tg = lane & 3;
    const int bn = blockIdx.x * 128, bm = blockIdx.y * 128;
    const int H = N >> 2;

    float acc[4][4][4];
#pragma unroll
    for (int a = 0; a < 4; a++)
#pragma unroll
        for (int b = 0; b < 4; b++)
#pragma unroll
            for (int c = 0; c < 4; c++) acc[a][b][c] = 0.f;

    const int NK = K >> 5;

#pragma unroll
    for (int i = 0; i < 4; i++) {
        int id = tid + i * 256, row = id >> 3, c4 = id & 7;
        cp_async16(&As[row * 36 + c4 * 4], A + (size_t)(bm + row) * K + c4 * 4);
        int np = bn + row;
        int srow = (np & 3) * H + (np >> 2);
        cp_async16(&Bs[row * 36 + c4 * 4], W + (size_t)srow * K + c4 * 4);
    }
    CP_COMMIT();

    int buf = 0;
    for (int kt = 0; kt < NK; kt++) {
        CP_WAIT0();
        __syncthreads();
        if (kt + 1 < NK) {
            int koff = (kt + 1) * 32;
            int nb = buf ^ 1;
#pragma unroll
            for (int i = 0; i < 4; i++) {
                int id = tid + i * 256, row = id >> 3, c4 = id & 7;
                cp_async16(&As[nb * 128 * 36 + row * 36 + c4 * 4],
                           A + (size_t)(bm + row) * K + koff + c4 * 4);
                int np = bn + row;
                int srow = (np & 3) * H + (np >> 2);
                cp_async16(&Bs[nb * 128 * 36 + row * 36 + c4 * 4],
                           W + (size_t)srow * K + koff + c4 * 4);
            }
        }
        CP_COMMIT();

        const unsigned* Ab = As + buf * 128 * 36;
        const unsigned* Bb = Bs + buf * 128 * 36;
#pragma unroll
        for (int ks = 0; ks < 4; ks++) {
            unsigned af[4][4], bf[4][2];
#pragma unroll
            for (int mt = 0; mt < 4; mt++) {
                int r = wm * 64 + mt * 16 + g;
                af[mt][0] = Ab[r * 36 + ks * 8 + tg];
                af[mt][1] = Ab[(r + 8) * 36 + ks * 8 + tg];
                af[mt][2] = Ab[r * 36 + ks * 8 + tg + 4];
                af[mt][3] = Ab[(r + 8) * 36 + ks * 8 + tg + 4];
            }
#pragma unroll
            for (int nt = 0; nt < 4; nt++) {
                int nl = wn * 32 + nt * 8 + g;
                bf[nt][0] = Bb[nl * 36 + ks * 8 + tg];
                bf[nt][1] = Bb[nl * 36 + ks * 8 + tg + 4];
            }
#pragma unroll
            for (int mt = 0; mt < 4; mt++)
#pragma unroll
                for (int nt = 0; nt < 4; nt++)
                    mma_tf32(acc[mt][nt], af[mt], bf[nt]);
        }
        buf ^= 1;
    }

#pragma unroll
    for (int mt = 0; mt < 4; mt++) {
        int r0 = bm + wm * 64 + mt * 16 + g;
#pragma unroll
        for (int nt = 0; nt < 4; nt++) {
            int c = bn + wn * 32 + nt * 8 + tg * 2;
            int s0 = (c & 3) * H + (c >> 2);
            int s1 = ((c + 1) & 3) * H + ((c + 1) >> 2);
            float bb0 = b1[s0] + b2[s0];
            float bb1 = b1[s1] + b2[s1];
            C[(size_t)r0 * N + c]           = acc[mt][nt][0] + bb0;
            C[(size_t)r0 * N + c + 1]       = acc[mt][nt][1] + bb1;
            C[(size_t)(r0 + 8) * N + c]     = acc[mt][nt][2] + bb0;
            C[(size_t)(r0 + 8) * N + c + 1] = acc[mt][nt][3] + bb1;
        }
    }
}

// ---------------- fused dual-layer LSTM recurrence ----------------
// 128 CTAs = 16 clusters of 8, 512 threads each.
// Blocks 0-63:   layer1 (8 batch-groups x 8 ranks, 32 units/rank, k=256 split 2)
//   -> writes out1[b][t][j], releases g_flag1[bg] (8 arrivals per step).
// Blocks 64-127: layer2 (8 batch-groups x 8 ranks, 16 units/rank), per step:
//   acquire flag, cp.async out1 rows, MMA over concat k=[out1(t) (256); h2(t-1) (128)]
//   split 4 ways, biases folded at update. No xg2 / GEMM2 at all.
__global__ void __launch_bounds__(512, 1) __cluster_dims__(8, 1, 1)
fused_recur(const float* __restrict__ xg1,   // [b][t][j*4+g] (layer1 gates)
            const float* __restrict__ Whh1,  // [1024][256]
            const float* __restrict__ Wih2,  // [512][256]
            const float* __restrict__ Whh2,  // [512][128]
            const float* __restrict__ bih2,  // [512]
            const float* __restrict__ bhh2,  // [512]
            float* __restrict__ out1,        // [b][t][256]
            float* __restrict__ h2f,         // [64][128]
            unsigned* __restrict__ flag1,    // [8]
            int T)
{
    extern __shared__ unsigned sm[];
    const int tid = threadIdx.x, lane = tid & 31, warp = tid >> 5;
    const int g = lane >> 2, tg = lane & 3;
    const uint32_t rank = my_ctarank();

    if (blockIdx.x < 64) {
        // ================= LAYER 1 =================
        constexpr int HDP = 260;           // padded h stride (words)
        unsigned* hs = sm;                 // [2][8][260]
        float* part  = (float*)(sm + 2 * 8 * HDP);  // [16][132]

        const int wm = warp & 7, wk = warp >> 3;
        const int jbase = (int)rank * 32;
        const int bg = blockIdx.x >> 3, bglob0 = bg * 8;

        // weight fragments (k-half per warp): 16 k-steps x 4 regs
        unsigned areg[16][4];
        {
            int lr0 = wm * 16 + g, lr1 = lr0 + 8;
            const float* w0 = Whh1 + (size_t)((lr0 & 3) * 256 + jbase + (lr0 >> 2)) * 256 + wk * 128;
            const float* w1 = Whh1 + (size_t)((lr1 & 3) * 256 + jbase + (lr1 >> 2)) * 256 + wk * 128;
#pragma unroll
            for (int ks = 0; ks < 16; ks++) {
                areg[ks][0] = f2tf32(w0[ks * 8 + tg]);
                areg[ks][1] = f2tf32(w1[ks * 8 + tg]);
                areg[ks][2] = f2tf32(w0[ks * 8 + tg + 4]);
                areg[ks][3] = f2tf32(w1[ks * 8 + tg + 4]);
            }
        }

        for (int i = tid; i < 2 * 8 * HDP; i += 512) hs[i] = 0u;
        __syncthreads();
        CLUSTER_ARRIVE();
        CLUSTER_WAIT();

        const int ub = tid >> 5, ujl = tid & 31;  // updater: tid<256
        const float* xgp = xg1 + ((size_t)(bglob0 + (ub & 7)) * T) * 1024 + (jbase + ujl) * 4;
        const uint32_t hs_base = smem_u32(hs);
        float cc = 0.f;
        float4 xv = make_float4(0.f, 0.f, 0.f, 0.f);
        if (tid < 256) xv = *(const float4*)xgp;

        for (int t = 0; t < T; t++) {
            const int rb = t & 1, wb = rb ^ 1;

            // MMA: rows [wm*16,+16), k-half wk, cols = 8 batches
            {
                float acc[4][4];
#pragma unroll
                for (int ch = 0; ch < 4; ch++)
#pragma unroll
                    for (int i = 0; i < 4; i++) acc[ch][i] = 0.f;
                const unsigned* hb = hs + rb * 8 * HDP + g * HDP + wk * 128;
#pragma unroll
                for (int ks = 0; ks < 16; ks++) {
                    unsigned bf[2];
                    bf[0] = hb[ks * 8 + tg];
                    bf[1] = hb[ks * 8 + tg + 4];
                    mma_tf32(acc[ks & 3], areg[ks], bf);
                }
                float s0 = (acc[0][0] + acc[1][0]) + (acc[2][0] + acc[3][0]);
                float s1 = (acc[0][1] + acc[1][1]) + (acc[2][1] + acc[3][1]);
                float s2 = (acc[0][2] + acc[1][2]) + (acc[2][2] + acc[3][2]);
                float s3 = (acc[0][3] + acc[1][3]) + (acc[2][3] + acc[3][3]);
                int lr = wm * 16 + g;
                part[(wk * 8 + tg * 2 + 0) * 132 + lr]     = s0;
                part[(wk * 8 + tg * 2 + 1) * 132 + lr]     = s1;
                part[(wk * 8 + tg * 2 + 0) * 132 + lr + 8] = s2;
                part[(wk * 8 + tg * 2 + 1) * 132 + lr + 8] = s3;
            }
            __syncthreads();

            if (tid < 256) {
                float4 p0 = *(const float4*)(part + (0 + ub) * 132 + ujl * 4);
                float4 p1 = *(const float4*)(part + (8 + ub) * 132 + ujl * 4);
                float iv = fsigmoid(p0.x + p1.x + xv.x);
                float fv = fsigmoid(p0.y + p1.y + xv.y);
                float gv = ftanh  (p0.z + p1.z + xv.z);
                float ov = fsigmoid(p0.w + p1.w + xv.w);
                cc = fv * cc + iv * gv;
                float hval = ov * ftanh(cc);
                unsigned hbits = f2tf32(hval);
                hs[(wb * 8 + ub) * HDP + jbase + ujl] = hbits;
                out1[((size_t)(bglob0 + ub) * T + t) * 256 + jbase + ujl] =
                    __uint_as_float(hbits);
            }
            __syncthreads();

            if (tid == 0) red_release_gpu_add(flag1 + bg);

            // broadcast own 8x32 slice (64 float4) to 7 peers
            if (tid < 448) {
                int pr  = tid >> 6;            // 0..6
                int rem = tid & 63;
                int bb  = rem >> 3, k4 = rem & 7;
                pr += (pr >= (int)rank);
                uint32_t laddr = hs_base +
                    4u * (uint32_t)((wb * 8 + bb) * HDP + jbase + 4 * k4);
                uint32_t raddr;
                asm("mapa.shared::cluster.u32 %0, %1, %2;"
                    : "=r"(raddr) : "r"(laddr), "r"(pr));
                float4 v;
                asm volatile("ld.shared.v4.f32 {%0,%1,%2,%3}, [%4];"
                             : "=f"(v.x), "=f"(v.y), "=f"(v.z), "=f"(v.w)
                             : "r"(laddr));
                asm volatile("st.shared::cluster.v4.f32 [%0], {%1,%2,%3,%4};"
                             :: "r"(raddr), "f"(v.x), "f"(v.y), "f"(v.z), "f"(v.w)
                             : "memory");
            }

            CLUSTER_ARRIVE();
            if (tid < 256 && t + 1 < T)
                xv = *(const float4*)(xgp + (size_t)(t + 1) * 1024);
            CLUSTER_WAIT();
        }
    } else {
        // ================= LAYER 2 =================
        constexpr int HDP = 132;           // padded h2 stride (words)
        constexpr int OP  = 268;           // padded out1 row stride (words)
        unsigned* h2s = sm;                          // [2][8][132]
        unsigned* o1s = sm + 2 * 8 * HDP;            // [8][268]
        float* part   = (float*)(o1s + 8 * OP);      // [32][68]

        const int wm = warp & 3, wk = warp >> 2;
        const int jbase = (int)rank * 16;
        const int bg = (blockIdx.x >> 3) - 8, bglob0 = bg * 8;

        // weight fragments: input part (k 256 -> 64/warp -> 8 ks), recurrent (128 -> 32/warp -> 4 ks)
        unsigned aregI[8][4], aregH[4][4];
        {
            int lr0 = wm * 16 + g, lr1 = lr0 + 8;
            int sr0 = (lr0 & 3) * 128 + jbase + (lr0 >> 2);
            int sr1 = (lr1 & 3) * 128 + jbase + (lr1 >> 2);
            const float* wi0 = Wih2 + (size_t)sr0 * 256 + wk * 64;
            const float* wi1 = Wih2 + (size_t)sr1 * 256 + wk * 64;
#pragma unroll
            for (int ks = 0; ks < 8; ks++) {
                aregI[ks][0] = f2tf32(wi0[ks * 8 + tg]);
                aregI[ks][1] = f2tf32(wi1[ks * 8 + tg]);
                aregI[ks][2] = f2tf32(wi0[ks * 8 + tg + 4]);
                aregI[ks][3] = f2tf32(wi1[ks * 8 + tg + 4]);
            }
            const float* wh0 = Whh2 + (size_t)sr0 * 128 + wk * 32;
            const float* wh1 = Whh2 + (size_t)sr1 * 128 + wk * 32;
#pragma unroll
            for (int ks = 0; ks < 4; ks++) {
                aregH[ks][0] = f2tf32(wh0[ks * 8 + tg]);
                aregH[ks][1] = f2tf32(wh1[ks * 8 + tg]);
                aregH[ks][2] = f2tf32(wh0[ks * 8 + tg + 4]);
                aregH[ks][3] = f2tf32(wh1[ks * 8 + tg + 4]);
            }
        }

        // bias for updater threads
        float4 bv = make_float4(0.f, 0.f, 0.f, 0.f);
        const int ub = tid >> 4, ujl = tid & 15;   // tid<128
        if (tid < 128) {
            int j = jbase + ujl;
            bv.x = bih2[0 * 128 + j] + bhh2[0 * 128 + j];
            bv.y = bih2[1 * 128 + j] + bhh2[1 * 128 + j];
            bv.z = bih2[2 * 128 + j] + bhh2[2 * 128 + j];
            bv.w = bih2[3 * 128 + j] + bhh2[3 * 128 + j];
        }

        for (int i = tid; i < 2 * 8 * HDP; i += 512) h2s[i] = 0u;
        __syncthreads();
        CLUSTER_ARRIVE();
        CLUSTER_WAIT();

        const uint32_t h2s_base = smem_u32(h2s);
        float cc = 0.f;

        for (int t = 0; t < T; t++) {
            const int rb = t & 1, wb = rb ^ 1;

            // wait for layer1 step t (usually already done)
            if (tid == 0) {
                unsigned tgt = 8u * (unsigned)(t + 1);
                while (ld_acquire_gpu(flag1 + bg) < tgt) { __nanosleep(40); }
            }
            __syncthreads();

            // fetch out1 rows for this group's 8 batches (8 KB, 1 float4/thread)
            {
                int bb = tid >> 6, k4 = tid & 63;
                cp_async16(o1s + bb * OP + k4 * 4,
                           out1 + ((size_t)(bglob0 + bb) * T + t) * 256 + k4 * 4);
                CP_COMMIT();
            }

            float acc[4][4];
#pragma unroll
            for (int ch = 0; ch < 4; ch++)
#pragma unroll
                for (int i = 0; i < 4; i++) acc[ch][i] = 0.f;

            // recurrent-k MMA first (hides out1 cp.async latency)
            {
                const unsigned* hb = h2s + rb * 8 * HDP + g * HDP + wk * 32;
#pragma unroll
                for (int ks = 0; ks < 4; ks++) {
                    unsigned bf[2];
                    bf[0] = hb[ks * 8 + tg];
                    bf[1] = hb[ks * 8 + tg + 4];
                    mma_tf32(acc[ks], aregH[ks], bf);
                }
            }
            CP_WAIT0();
            __syncthreads();

            // input-k MMA over out1(t)
            {
                const unsigned* ob = o1s + g * OP + wk * 64;
#pragma unroll
                for (int ks = 0; ks < 8; ks++) {
                    unsigned bf[2];
                    bf[0] = ob[ks * 8 + tg];
                    bf[1] = ob[ks * 8 + tg + 4];
                    mma_tf32(acc[ks & 3], aregI[ks], bf);
                }
            }
            {
                float s0 = (acc[0][0] + acc[1][0]) + (acc[2][0] + acc[3][0]);
                float s1 = (acc[0][1] + acc[1][1]) + (acc[2][1] + acc[3][1]);
                float s2 = (acc[0][2] + acc[1][2]) + (acc[2][2] + acc[3][2]);
                float s3 = (acc[0][3] + acc[1][3]) + (acc[2][3] + acc[3][3]);
                int lr = wm * 16 + g;
                part[(wk * 8 + tg * 2 + 0) * 68 + lr]     = s0;
                part[(wk * 8 + tg * 2 + 1) * 68 + lr]     = s1;
                part[(wk * 8 + tg * 2 + 0) * 68 + lr + 8] = s2;
                part[(wk * 8 + tg * 2 + 1) * 68 + lr + 8] = s3;
            }
            __syncthreads();

            if (tid < 128) {
                float4 q0 = *(const float4*)(part + ( 0 + ub) * 68 + ujl * 4);
                float4 q1 = *(const float4*)(part + ( 8 + ub) * 68 + ujl * 4);
                float4 q2 = *(const float4*)(part + (16 + ub) * 68 + ujl * 4);
                float4 q3 = *(const float4*)(part + (24 + ub) * 68 + ujl * 4);
                float iv = fsigmoid(((q0.x + q1.x) + (q2.x + q3.x)) + bv.x);
                float fv = fsigmoid(((q0.y + q1.y) + (q2.y + q3.y)) + bv.y);
                float gv = ftanh  (((q0.z + q1.z) + (q2.z + q3.z)) + bv.z);
                float ov = fsigmoid(((q0.w + q1.w) + (q2.w + q3.w)) + bv.w);
                cc = fv * cc + iv * gv;
                float hval = ov * ftanh(cc);
                unsigned hbits = f2tf32(hval);
                h2s[(wb * 8 + ub) * HDP + jbase + ujl] = hbits;
                if (t == T - 1)
                    h2f[(size_t)(bglob0 + ub) * 128 + jbase + ujl] = __uint_as_float(hbits);
            }
            __syncthreads();

            // broadcast own 8x16 slice (32 float4) to 7 peers
            if (tid < 224) {
                int pr  = tid >> 5;            // 0..6
                int rem = tid & 31;
                int bb  = rem >> 2, k4 = rem & 3;
                pr += (pr >= (int)rank);
                uint32_t laddr = h2s_base +
                    4u * (uint32_t)((wb * 8 + bb) * HDP + jbase + 4 * k4);
                uint32_t raddr;
                asm("mapa.shared::cluster.u32 %0, %1, %2;"
                    : "=r"(raddr) : "r"(laddr), "r"(pr));
                float4 v;
                asm volatile("ld.shared.v4.f32 {%0,%1,%2,%3}, [%4];"
                             : "=f"(v.x), "=f"(v.y), "=f"(v.z), "=f"(v.w)
                             : "r"(laddr));
                asm volatile("st.shared::cluster.v4.f32 [%0], {%1,%2,%3,%4};"
                             :: "r"(raddr), "f"(v.x), "f"(v.y), "f"(v.z), "f"(v.w)
                             : "memory");
            }

            CLUSTER_ARRIVE();
            CLUSTER_WAIT();
        }
    }
}

// ---------------- FC head ----------------
__global__ void fc_head(const float* __restrict__ h2,     // [64][128]
                        const float* __restrict__ Wfc,    // [64][128]
                        const float* __restrict__ bfc,    // [64]
                        const float* __restrict__ Wout,   // [1][64]
                        const float* __restrict__ bout,   // [1]
                        float* __restrict__ outp)         // [64]
{
    int b = threadIdx.x;  // 64 threads
    const float* hr = h2 + b * 128;
    float acc = 0.f;
    for (int uu = 0; uu < 64; uu++) {
        const float* wr = Wfc + uu * 128;
        float s0 = 0.f, s1 = 0.f, s2 = 0.f, s3 = 0.f;
#pragma unroll 8
        for (int k = 0; k < 128; k += 4) {
            s0 += hr[k]     * wr[k];
            s1 += hr[k + 1] * wr[k + 1];
            s2 += hr[k + 2] * wr[k + 2];
            s3 += hr[k + 3] * wr[k + 3];
        }
        float s = (s0 + s1) + (s2 + s3) + bfc[uu];
        acc += fmaxf(s, 0.f) * Wout[uu];
    }
    outp[b] = acc + bout[0];
}

// ---------------- launch ----------------
extern "C" void kernel_launch(void* const* d_in, const int* in_sizes, int n_in,
                              void* d_out, int out_size)
{
    const float* x    = (const float*)d_in[0];
    const float* Wih1 = (const float*)d_in[1];
    const float* Whh1 = (const float*)d_in[2];
    const float* bih1 = (const float*)d_in[3];
    const float* bhh1 = (const float*)d_in[4];
    const float* Wih2 = (const float*)d_in[5];
    const float* Whh2 = (const float*)d_in[6];
    const float* bih2 = (const float*)d_in[7];
    const float* bhh2 = (const float*)d_in[8];
    const float* Wfc1 = (const float*)d_in[9];
    const float* bfc1 = (const float*)d_in[10];
    const float* Wout = (const float*)d_in[11];
    const float* bout = (const float*)d_in[12];
    float* outp = (float*)d_out;

    float *xg1, *out1, *w1cv, *h2f;
    unsigned* flag1;
    cudaGetSymbolAddress((void**)&xg1,   g_xg1);
    cudaGetSymbolAddress((void**)&out1,  g_out1);
    cudaGetSymbolAddress((void**)&w1cv,  g_w1cv);
    cudaGetSymbolAddress((void**)&h2f,   g_h2f);
    cudaGetSymbolAddress((void**)&flag1, g_flag1);

    const int GEMM_SMEM  = 2 * 128 * 36 * 4 * 2;  // 73728 B
    // layer1: 2*8*260*4 + 16*132*4 = 16640 + 8448 = 25088
    // layer2: 2*8*132*4 + 8*268*4 + 32*68*4 = 8448 + 8576 + 8704 = 25728
    const int FUSE_SMEM  = 25728;
    cudaFuncSetAttribute(gemm_tf32_perm,
                         cudaFuncAttributeMaxDynamicSharedMemorySize, GEMM_SMEM);
    cudaFuncSetAttribute(fused_recur,
                         cudaFuncAttributeMaxDynamicSharedMemorySize, 64 * 1024);

    cudaMemsetAsync(flag1, 0, 8 * sizeof(unsigned));

    // prep: round GEMM1 weights to tf32
    cvt_rna_kernel<<<(1024 * 2048 + 255) / 256, 256>>>(Wih1, w1cv, 1024 * 2048);

    const int M = 64 * 512;

    // layer 1 input projection
    gemm_tf32_perm<<<dim3(1024 / 128, M / 128), 256, GEMM_SMEM>>>(
        x, w1cv, bih1, bhh1, xg1, M, 1024, 2048);

    // fused layer1 + layer2 recurrence (layer2 streams one step behind layer1)
    fused_recur<<<128, 512, FUSE_SMEM>>>(
        xg1, Whh1, Wih2, Whh2, bih2, bhh2, out1, h2f, flag1, 512);

    // FC head
    fc_head<<<1, 64>>>(h2f, Wfc1, bfc1, Wout, bout, outp);
}

// round 8
// speedup vs baseline: 1.2846x; 1.2846x over previous
#include <cuda_runtime.h>
#include <math.h>
#include <stdint.h>

// ---------------- static device scratch (no allocation allowed) ----------------
__device__ float    g_xg1 [(size_t)32768 * 1024];   // layer1 input projection, layout [b][t][j*4+g]
__device__ float    g_out1[(size_t)32768 * 256];    // layer1 hidden outputs [b][t][j] (tf32-rounded)
__device__ float    g_xg2 [(size_t)32768 * 512];    // layer2 input projection [b][t][j*4+g]
__device__ float    g_w1cv[(size_t)1024 * 2048];    // Wih1 rounded to tf32
__device__ float    g_w2cv[(size_t)512 * 256];      // Wih2 rounded to tf32
__device__ float    g_h2f [64 * 128];               // final layer2 h

// ---------------- helpers ----------------
__device__ __forceinline__ unsigned f2tf32(float f) {
    unsigned r;
    asm("cvt.rna.tf32.f32 %0, %1;" : "=r"(r) : "f"(f));
    return r;
}

__device__ __forceinline__ void mma_tf32(float* c, const unsigned* a, const unsigned* b) {
    asm volatile(
        "mma.sync.aligned.m16n8k8.row.col.f32.tf32.tf32.f32 "
        "{%0,%1,%2,%3},{%4,%5,%6,%7},{%8,%9},{%0,%1,%2,%3};"
        : "+f"(c[0]), "+f"(c[1]), "+f"(c[2]), "+f"(c[3])
        : "r"(a[0]), "r"(a[1]), "r"(a[2]), "r"(a[3]), "r"(b[0]), "r"(b[1]));
}

__device__ __forceinline__ void cp_async16(void* smem_dst, const void* gptr) {
    unsigned s = (unsigned)__cvta_generic_to_shared(smem_dst);
    asm volatile("cp.async.cg.shared.global [%0], [%1], 16;\n" :: "r"(s), "l"(gptr));
}
#define CP_COMMIT() asm volatile("cp.async.commit_group;\n" ::: "memory")
#define CP_WAIT0()  asm volatile("cp.async.wait_group 0;\n" ::: "memory")

__device__ __forceinline__ uint32_t smem_u32(const void* p) {
    return (uint32_t)__cvta_generic_to_shared(p);
}
__device__ __forceinline__ uint32_t my_ctarank() {
    uint32_t r;
    asm("mov.u32 %0, %%cluster_ctarank;" : "=r"(r));
    return r;
}
#define CLUSTER_ARRIVE() asm volatile("barrier.cluster.arrive.aligned;" ::: "memory")
#define CLUSTER_WAIT()   asm volatile("barrier.cluster.wait.aligned;" ::: "memory")

// fast precise activations (MUFU ex2 + rcp; err ~1e-6)
__device__ __forceinline__ float fsigmoid(float x) {
    return 1.f / (1.f + __expf(-x));
}
__device__ __forceinline__ float ftanh(float x) {
    return 1.f - 2.f / (1.f + __expf(2.f * x));
}

// ---------------- prep: round weights to tf32 once ----------------
__global__ void cvt_rna_kernel(const float* __restrict__ src, float* __restrict__ dst, int n) {
    int i = blockIdx.x * 256 + threadIdx.x;
    if (i < n) dst[i] = __uint_as_float(f2tf32(src[i]));
}

// ---------------- tf32 GEMM with permuted output columns ----------------
__global__ void __launch_bounds__(256, 2) gemm_tf32_perm(
    const float* __restrict__ A, const float* __restrict__ W,
    const float* __restrict__ b1, const float* __restrict__ b2,
    float* __restrict__ C, int M, int N, int K)
{
    extern __shared__ unsigned sh[];
    unsigned* As = sh;                 // [2][128][36]
    unsigned* Bs = sh + 2 * 128 * 36;  // [2][128][36]

    const int tid = threadIdx.x, lane = tid & 31, warp = tid >> 5;
    const int wm = warp & 1, wn = warp >> 1;
    const int g = lane >> 2, tg = lane & 3;
    const int bn = blockIdx.x * 128, bm = blockIdx.y * 128;
    const int H = N >> 2;

    float acc[4][4][4];
#pragma unroll
    for (int a = 0; a < 4; a++)
#pragma unroll
        for (int b = 0; b < 4; b++)
#pragma unroll
            for (int c = 0; c < 4; c++) acc[a][b][c] = 0.f;

    const int NK = K >> 5;

#pragma unroll
    for (int i = 0; i < 4; i++) {
        int id = tid + i * 256, row = id >> 3, c4 = id & 7;
        cp_async16(&As[row * 36 + c4 * 4], A + (size_t)(bm + row) * K + c4 * 4);
        int np = bn + row;
        int srow = (np & 3) * H + (np >> 2);
        cp_async16(&Bs[row * 36 + c4 * 4], W + (size_t)srow * K + c4 * 4);
    }
    CP_COMMIT();

    int buf = 0;
    for (int kt = 0; kt < NK; kt++) {
        CP_WAIT0();
        __syncthreads();
        if (kt + 1 < NK) {
            int koff = (kt + 1) * 32;
            int nb = buf ^ 1;
#pragma unroll
            for (int i = 0; i < 4; i++) {
                int id = tid + i * 256, row = id >> 3, c4 = id & 7;
                cp_async16(&As[nb * 128 * 36 + row * 36 + c4 * 4],
                           A + (size_t)(bm + row) * K + koff + c4 * 4);
                int np = bn + row;
                int srow = (np & 3) * H + (np >> 2);
                cp_async16(&Bs[nb * 128 * 36 + row * 36 + c4 * 4],
                           W + (size_t)srow * K + koff + c4 * 4);
            }
        }
        CP_COMMIT();

        const unsigned* Ab = As + buf * 128 * 36;
        const unsigned* Bb = Bs + buf * 128 * 36;
#pragma unroll
        for (int ks = 0; ks < 4; ks++) {
            unsigned af[4][4], bf[4][2];
#pragma unroll
            for (int mt = 0; mt < 4; mt++) {
                int r = wm * 64 + mt * 16 + g;
                af[mt][0] = Ab[r * 36 + ks * 8 + tg];
                af[mt][1] = Ab[(r + 8) * 36 + ks * 8 + tg];
                af[mt][2] = Ab[r * 36 + ks * 8 + tg + 4];
                af[mt][3] = Ab[(r + 8) * 36 + ks * 8 + tg + 4];
            }
#pragma unroll
            for (int nt = 0; nt < 4; nt++) {
                int nl = wn * 32 + nt * 8 + g;
                bf[nt][0] = Bb[nl * 36 + ks * 8 + tg];
                bf[nt][1] = Bb[nl * 36 + ks * 8 + tg + 4];
            }
#pragma unroll
            for (int mt = 0; mt < 4; mt++)
#pragma unroll
                for (int nt = 0; nt < 4; nt++)
                    mma_tf32(acc[mt][nt], af[mt], bf[nt]);
        }
        buf ^= 1;
    }

#pragma unroll
    for (int mt = 0; mt < 4; mt++) {
        int r0 = bm + wm * 64 + mt * 16 + g;
#pragma unroll
        for (int nt = 0; nt < 4; nt++) {
            int c = bn + wn * 32 + nt * 8 + tg * 2;
            int s0 = (c & 3) * H + (c >> 2);
            int s1 = ((c + 1) & 3) * H + ((c + 1) >> 2);
            float bb0 = b1[s0] + b2[s0];
            float bb1 = b1[s1] + b2[s1];
            C[(size_t)r0 * N + c]           = acc[mt][nt][0] + bb0;
            C[(size_t)r0 * N + c + 1]       = acc[mt][nt][1] + bb1;
            C[(size_t)(r0 + 8) * N + c]     = acc[mt][nt][2] + bb0;
            C[(size_t)(r0 + 8) * N + c + 1] = acc[mt][nt][3] + bb1;
        }
    }
}

// ---------------- cluster-based LSTM recurrence (Round-6 version) ----------------
template <int HD, int JPC, int NT, bool STORE_OUT>
__global__ void __launch_bounds__(NT, 1) __cluster_dims__(8, 1, 1)
lstm_recur_cl2(const float* __restrict__ xg,    // [b][t][j*4+g]
               const float* __restrict__ Whh,   // [4*HD][HD]
               float* __restrict__ out,         // [b][t][HD] (layer1) or null
               float* __restrict__ hfin,        // [64][HD] final h (layer2) or null
               int T)
{
    constexpr int KS  = HD / 8;        // mma k-steps
    constexpr int HDP = HD + 4;        // padded h row stride
    constexpr int RP  = 4 * JPC + 4;   // padded partial row stride
    constexpr int NG  = JPC / 4;       // float4 per batch in own slice
    constexpr int CPY = 7 * 8 * NG;    // remote float4 copies per step

    extern __shared__ unsigned smem_u[];
    unsigned* hs = smem_u;                       // [2][8][HDP] tf32 h
    float* part  = (float*)(hs + 2 * 8 * HDP);   // [8][RP]

    const int tid = threadIdx.x, lane = tid & 31, warp = tid >> 5;
    const int g = lane >> 2, tg = lane & 3;
    const uint32_t rank = my_ctarank();
    const int bg = blockIdx.x >> 3;
    const int jbase = (int)rank * JPC;
    const int bglob0 = bg * 8;

    // ---- preload weight fragments into registers (once) ----
    unsigned areg[KS][4];
    {
        int lr0 = warp * 16 + g, lr1 = lr0 + 8;
        const float* w0 = Whh + (size_t)((lr0 & 3) * HD + jbase + (lr0 >> 2)) * HD;
        const float* w1 = Whh + (size_t)((lr1 & 3) * HD + jbase + (lr1 >> 2)) * HD;
#pragma unroll
        for (int ks = 0; ks < KS; ks++) {
            areg[ks][0] = f2tf32(w0[ks * 8 + tg]);
            areg[ks][1] = f2tf32(w1[ks * 8 + tg]);
            areg[ks][2] = f2tf32(w0[ks * 8 + tg + 4]);
            areg[ks][3] = f2tf32(w1[ks * 8 + tg + 4]);
        }
    }

    // zero both h buffers
    for (int i = tid; i < 2 * 8 * HDP; i += NT) hs[i] = 0u;
    __syncthreads();
    CLUSTER_ARRIVE();
    CLUSTER_WAIT();

    // updater mapping: one (batch, unit) per thread (NT == 8*JPC)
    const int b  = tid / JPC;
    const int jl = tid % JPC;
    const float* xgp = xg + ((size_t)(bglob0 + b) * T) * (4 * HD) + (jbase + jl) * 4;
    const uint32_t hs_base = smem_u32(hs);
    float cc = 0.f;
    float4 xv = *(const float4*)xgp;   // step 0 gates

    for (int t = 0; t < T; t++) {
        const int rb = t & 1, wb = rb ^ 1;

        // ---- mma: rows [warp*16,+16) x 8 batches, 4 accumulator chains ----
        {
            float acc[4][4];
#pragma unroll
            for (int ch = 0; ch < 4; ch++)
#pragma unroll
                for (int i = 0; i < 4; i++) acc[ch][i] = 0.f;

            const unsigned* hb = hs + rb * 8 * HDP + g * HDP;  // batch g
#pragma unroll
            for (int ks = 0; ks < KS; ks++) {
                unsigned bf[2];
                bf[0] = hb[ks * 8 + tg];
                bf[1] = hb[ks * 8 + tg + 4];
                mma_tf32(acc[ks & 3], areg[ks], bf);
            }
            float s0 = (acc[0][0] + acc[1][0]) + (acc[2][0] + acc[3][0]);
            float s1 = (acc[0][1] + acc[1][1]) + (acc[2][1] + acc[3][1]);
            float s2 = (acc[0][2] + acc[1][2]) + (acc[2][2] + acc[3][2]);
            float s3 = (acc[0][3] + acc[1][3]) + (acc[2][3] + acc[3][3]);
            int lr = warp * 16 + g;
            part[(tg * 2 + 0) * RP + lr]     = s0;
            part[(tg * 2 + 1) * RP + lr]     = s1;
            part[(tg * 2 + 0) * RP + lr + 8] = s2;
            part[(tg * 2 + 1) * RP + lr + 8] = s3;
        }
        __syncthreads();

        // ---- update one (batch, unit); stage h locally ----
        {
            float4 p = *(const float4*)(part + b * RP + jl * 4);  // gates i,f,c,o
            float iv = fsigmoid(p.x + xv.x);
            float fv = fsigmoid(p.y + xv.y);
            float gv = ftanh(p.z + xv.z);
            float ov = fsigmoid(p.w + xv.w);
            cc = fv * cc + iv * gv;
            float hval = ov * ftanh(cc);
            unsigned hbits = f2tf32(hval);
            hs[(wb * 8 + b) * HDP + jbase + jl] = hbits;   // local store
            if (STORE_OUT)
                out[((size_t)(bglob0 + b) * T + t) * HD + jbase + jl] =
                    __uint_as_float(hbits);
            if (hfin && t == T - 1)
                hfin[(size_t)(bglob0 + b) * HD + jbase + jl] = __uint_as_float(hbits);
        }
        __syncthreads();

        // ---- cooperative float4 broadcast of own slice to 7 peers ----
        for (int i = tid; i < CPY; i += NT) {
            int pr  = i / (8 * NG);
            int rem = i - pr * (8 * NG);
            int bb  = rem / NG;
            int k4  = rem - bb * NG;
            pr += (pr >= (int)rank);   // skip self
            uint32_t laddr = hs_base +
                4u * (uint32_t)((wb * 8 + bb) * HDP + jbase + 4 * k4);
            uint32_t raddr;
            asm("mapa.shared::cluster.u32 %0, %1, %2;"
                : "=r"(raddr) : "r"(laddr), "r"(pr));
            float4 v;
            asm volatile("ld.shared.v4.f32 {%0,%1,%2,%3}, [%4];"
                         : "=f"(v.x), "=f"(v.y), "=f"(v.z), "=f"(v.w)
                         : "r"(laddr));
            asm volatile("st.shared::cluster.v4.f32 [%0], {%1,%2,%3,%4};"
                         :: "r"(raddr), "f"(v.x), "f"(v.y), "f"(v.z), "f"(v.w)
                         : "memory");
        }

        CLUSTER_ARRIVE();
        if (t + 1 < T)   // prefetch next step's gates under barrier skew
            xv = *(const float4*)(xgp + (size_t)(t + 1) * (4 * HD));
        CLUSTER_WAIT();
    }
}

// ---------------- FC head (parallel): 64 blocks x 64 threads ----------------
// Block b: stage h2[b][0:128] in smem; thread u computes dot(h2[b], Wfc[u]) with
// 4 ILP chains, relu * Wout[u]; tree-reduce 64 partials -> out[b].
__global__ void __launch_bounds__(64) fc_head_par(
    const float* __restrict__ h2,     // [64][128]
    const float* __restrict__ Wfc,    // [64][128]
    const float* __restrict__ bfc,    // [64]
    const float* __restrict__ Wout,   // [1][64]
    const float* __restrict__ bout,   // [1]
    float* __restrict__ outp)         // [64]
{
    __shared__ float hrs[128];
    __shared__ float red[64];
    const int b = blockIdx.x, u = threadIdx.x;

    // stage h row (2 floats per thread)
    ((float2*)hrs)[u] = ((const float2*)(h2 + b * 128))[u];
    __syncthreads();

    const float4* wr = (const float4*)(Wfc + u * 128);
    float s0 = 0.f, s1 = 0.f, s2 = 0.f, s3 = 0.f;
#pragma unroll
    for (int k = 0; k < 32; k += 4) {
        float4 w0 = wr[k],     w1 = wr[k + 1], w2 = wr[k + 2], w3 = wr[k + 3];
        const float* h0 = hrs + k * 4;
        s0 += w0.x * h0[0]  + w0.y * h0[1]  + w0.z * h0[2]  + w0.w * h0[3];
        s1 += w1.x * h0[4]  + w1.y * h0[5]  + w1.z * h0[6]  + w1.w * h0[7];
        s2 += w2.x * h0[8]  + w2.y * h0[9]  + w2.z * h0[10] + w2.w * h0[11];
        s3 += w3.x * h0[12] + w3.y * h0[13] + w3.z * h0[14] + w3.w * h0[15];
    }
    float s = (s0 + s1) + (s2 + s3) + bfc[u];
    red[u] = fmaxf(s, 0.f) * Wout[u];
    __syncthreads();

    // tree reduce 64 -> 1
    if (u < 32) {
        float v = red[u] + red[u + 32];
#pragma unroll
        for (int off = 16; off > 0; off >>= 1)
            v += __shfl_down_sync(0xffffffffu, v, off);
        if (u == 0) outp[b] = v + bout[0];
    }
}

// ---------------- launch ----------------
extern "C" void kernel_launch(void* const* d_in, const int* in_sizes, int n_in,
                              void* d_out, int out_size)
{
    const float* x    = (const float*)d_in[0];
    const float* Wih1 = (const float*)d_in[1];
    const float* Whh1 = (const float*)d_in[2];
    const float* bih1 = (const float*)d_in[3];
    const float* bhh1 = (const float*)d_in[4];
    const float* Wih2 = (const float*)d_in[5];
    const float* Whh2 = (const float*)d_in[6];
    const float* bih2 = (const float*)d_in[7];
    const float* bhh2 = (const float*)d_in[8];
    const float* Wfc1 = (const float*)d_in[9];
    const float* bfc1 = (const float*)d_in[10];
    const float* Wout = (const float*)d_in[11];
    const float* bout = (const float*)d_in[12];
    float* outp = (float*)d_out;

    float *xg1, *out1, *xg2, *w1cv, *w2cv, *h2f;
    cudaGetSymbolAddress((void**)&xg1,  g_xg1);
    cudaGetSymbolAddress((void**)&out1, g_out1);
    cudaGetSymbolAddress((void**)&xg2,  g_xg2);
    cudaGetSymbolAddress((void**)&w1cv, g_w1cv);
    cudaGetSymbolAddress((void**)&w2cv, g_w2cv);
    cudaGetSymbolAddress((void**)&h2f,  g_h2f);

    const int GEMM_SMEM = 2 * 128 * 36 * 4 * 2;                    // 73728 B
    const int R1_SMEM = (2 * 8 * 260) * 4 + 8 * 132 * 4;           // 20864 B
    const int R2_SMEM = (2 * 8 * 132) * 4 + 8 * 68 * 4;            // 10624 B
    cudaFuncSetAttribute(gemm_tf32_perm,
                         cudaFuncAttributeMaxDynamicSharedMemorySize, GEMM_SMEM);
    cudaFuncSetAttribute(lstm_recur_cl2<256, 32, 256, true>,
                         cudaFuncAttributeMaxDynamicSharedMemorySize, 64 * 1024);
    cudaFuncSetAttribute(lstm_recur_cl2<128, 16, 128, false>,
                         cudaFuncAttributeMaxDynamicSharedMemorySize, 64 * 1024);

    // prep: round input-projection weights to tf32
    cvt_rna_kernel<<<(1024 * 2048 + 255) / 256, 256>>>(Wih1, w1cv, 1024 * 2048);
    cvt_rna_kernel<<<(512 * 256 + 255) / 256, 256>>>(Wih2, w2cv, 512 * 256);

    const int M = 64 * 512;

    // layer 1 input projection
    gemm_tf32_perm<<<dim3(1024 / 128, M / 128), 256, GEMM_SMEM>>>(
        x, w1cv, bih1, bhh1, xg1, M, 1024, 2048);

    // layer 1 recurrence: 8 batch-groups x 8-CTA clusters
    lstm_recur_cl2<256, 32, 256, true><<<64, 256, R1_SMEM>>>(
        xg1, Whh1, out1, (float*)0, 512);

    // layer 2 input projection
    gemm_tf32_perm<<<dim3(512 / 128, M / 128), 256, GEMM_SMEM>>>(
        out1, w2cv, bih2, bhh2, xg2, M, 512, 256);

    // layer 2 recurrence
    lstm_recur_cl2<128, 16, 128, false><<<64, 128, R2_SMEM>>>(
        xg2, Whh2, (float*)0, h2f, 512);

    // FC head (parallel)
    fc_head_par<<<64, 64>>>(h2f, Wfc1, bfc1, Wout, bout, outp);
}

// round 9
// speedup vs baseline: 1.6098x; 1.2531x over previous
#include <cuda_runtime.h>
#include <math.h>
#include <stdint.h>

// ---------------- static device scratch (no allocation allowed) ----------------
__device__ float    g_xg1 [(size_t)32768 * 1024];   // layer1 input projection, layout [b][t][j*4+g]
__device__ float    g_out1[(size_t)32768 * 256];    // layer1 hidden outputs [b][t][j] (tf32-rounded)
__device__ float    g_xg2 [(size_t)32768 * 512];    // layer2 input projection [b][t][j*4+g]
__device__ float    g_w1cv[(size_t)1024 * 2048];    // Wih1 rounded to tf32
__device__ float    g_w2cv[(size_t)512 * 256];      // Wih2 rounded to tf32
__device__ float    g_h2f [64 * 128];               // final layer2 h

// ---------------- helpers ----------------
__device__ __forceinline__ unsigned f2tf32(float f) {
    unsigned r;
    asm("cvt.rna.tf32.f32 %0, %1;" : "=r"(r) : "f"(f));
    return r;
}

__device__ __forceinline__ void mma_tf32(float* c, const unsigned* a, const unsigned* b) {
    asm volatile(
        "mma.sync.aligned.m16n8k8.row.col.f32.tf32.tf32.f32 "
        "{%0,%1,%2,%3},{%4,%5,%6,%7},{%8,%9},{%0,%1,%2,%3};"
        : "+f"(c[0]), "+f"(c[1]), "+f"(c[2]), "+f"(c[3])
        : "r"(a[0]), "r"(a[1]), "r"(a[2]), "r"(a[3]), "r"(b[0]), "r"(b[1]));
}

__device__ __forceinline__ void cp_async16(void* smem_dst, const void* gptr) {
    unsigned s = (unsigned)__cvta_generic_to_shared(smem_dst);
    asm volatile("cp.async.cg.shared.global [%0], [%1], 16;\n" :: "r"(s), "l"(gptr));
}
#define CP_COMMIT() asm volatile("cp.async.commit_group;\n" ::: "memory")
#define CP_WAIT0()  asm volatile("cp.async.wait_group 0;\n" ::: "memory")

__device__ __forceinline__ uint32_t smem_u32(const void* p) {
    return (uint32_t)__cvta_generic_to_shared(p);
}
__device__ __forceinline__ uint32_t my_ctarank() {
    uint32_t r;
    asm("mov.u32 %0, %%cluster_ctarank;" : "=r"(r));
    return r;
}
#define CLUSTER_ARRIVE() asm volatile("barrier.cluster.arrive.aligned;" ::: "memory")
#define CLUSTER_WAIT()   asm volatile("barrier.cluster.wait.aligned;" ::: "memory")

__device__ __forceinline__ void mbar_init(uint32_t a, unsigned cnt) {
    asm volatile("mbarrier.init.shared.b64 [%0], %1;" :: "r"(a), "r"(cnt) : "memory");
}
__device__ __forceinline__ void mbar_expect_tx(uint32_t a, unsigned tx) {
    asm volatile("mbarrier.arrive.expect_tx.shared.b64 _, [%0], %1;"
                 :: "r"(a), "r"(tx) : "memory");
}
__device__ __forceinline__ void mbar_wait(uint32_t a, unsigned parity) {
    asm volatile(
        "{\n\t"
        ".reg .pred P1;\n\t"
        "WAIT_LOOP_%=:\n\t"
        "mbarrier.try_wait.parity.acquire.cta.shared::cta.b64 P1, [%0], %1, 0x989680;\n\t"
        "@P1 bra.uni WAIT_DONE_%=;\n\t"
        "bra.uni WAIT_LOOP_%=;\n\t"
        "WAIT_DONE_%=:\n\t"
        "}"
        :: "r"(a), "r"(parity) : "memory");
}
__device__ __forceinline__ void mbar_arrive_remote(uint32_t local_addr, int rank) {
    uint32_t ra;
    asm("mapa.shared::cluster.u32 %0, %1, %2;" : "=r"(ra) : "r"(local_addr), "r"(rank));
    asm volatile("mbarrier.arrive.shared::cluster.b64 _, [%0];" :: "r"(ra) : "memory");
}
__device__ __forceinline__ void st_async_b32(uint32_t local_dst, unsigned val,
                                             uint32_t local_mbar, int rank) {
    uint32_t ra, rm;
    asm("mapa.shared::cluster.u32 %0, %1, %2;" : "=r"(ra) : "r"(local_dst), "r"(rank));
    asm("mapa.shared::cluster.u32 %0, %1, %2;" : "=r"(rm) : "r"(local_mbar), "r"(rank));
    asm volatile("st.async.shared::cluster.mbarrier::complete_tx::bytes.b32 [%0], %1, [%2];"
                 :: "r"(ra), "r"(val), "r"(rm) : "memory");
}

// fast precise activations (MUFU ex2 + rcp; err ~1e-6)
__device__ __forceinline__ float fsigmoid(float x) {
    return 1.f / (1.f + __expf(-x));
}
__device__ __forceinline__ float ftanh(float x) {
    return 1.f - 2.f / (1.f + __expf(2.f * x));
}

// ---------------- prep: round weights to tf32 once ----------------
__global__ void cvt_rna_kernel(const float* __restrict__ src, float* __restrict__ dst, int n) {
    int i = blockIdx.x * 256 + threadIdx.x;
    if (i < n) dst[i] = __uint_as_float(f2tf32(src[i]));
}

// ---------------- tf32 GEMM with permuted output columns ----------------
__global__ void __launch_bounds__(256, 2) gemm_tf32_perm(
    const float* __restrict__ A, const float* __restrict__ W,
    const float* __restrict__ b1, const float* __restrict__ b2,
    float* __restrict__ C, int M, int N, int K)
{
    extern __shared__ unsigned sh[];
    unsigned* As = sh;                 // [2][128][36]
    unsigned* Bs = sh + 2 * 128 * 36;  // [2][128][36]

    const int tid = threadIdx.x, lane = tid & 31, warp = tid >> 5;
    const int wm = warp & 1, wn = warp >> 1;
    const int g = lane >> 2, tg = lane & 3;
    const int bn = blockIdx.x * 128, bm = blockIdx.y * 128;
    const int H = N >> 2;

    float acc[4][4][4];
#pragma unroll
    for (int a = 0; a < 4; a++)
#pragma unroll
        for (int b = 0; b < 4; b++)
#pragma unroll
            for (int c = 0; c < 4; c++) acc[a][b][c] = 0.f;

    const int NK = K >> 5;

#pragma unroll
    for (int i = 0; i < 4; i++) {
        int id = tid + i * 256, row = id >> 3, c4 = id & 7;
        cp_async16(&As[row * 36 + c4 * 4], A + (size_t)(bm + row) * K + c4 * 4);
        int np = bn + row;
        int srow = (np & 3) * H + (np >> 2);
        cp_async16(&Bs[row * 36 + c4 * 4], W + (size_t)srow * K + c4 * 4);
    }
    CP_COMMIT();

    int buf = 0;
    for (int kt = 0; kt < NK; kt++) {
        CP_WAIT0();
        __syncthreads();
        if (kt + 1 < NK) {
            int koff = (kt + 1) * 32;
            int nb = buf ^ 1;
#pragma unroll
            for (int i = 0; i < 4; i++) {
                int id = tid + i * 256, row = id >> 3, c4 = id & 7;
                cp_async16(&As[nb * 128 * 36 + row * 36 + c4 * 4],
                           A + (size_t)(bm + row) * K + koff + c4 * 4);
                int np = bn + row;
                int srow = (np & 3) * H + (np >> 2);
                cp_async16(&Bs[nb * 128 * 36 + row * 36 + c4 * 4],
                           W + (size_t)srow * K + koff + c4 * 4);
            }
        }
        CP_COMMIT();

        const unsigned* Ab = As + buf * 128 * 36;
        const unsigned* Bb = Bs + buf * 128 * 36;
#pragma unroll
        for (int ks = 0; ks < 4; ks++) {
            unsigned af[4][4], bf[4][2];
#pragma unroll
            for (int mt = 0; mt < 4; mt++) {
                int r = wm * 64 + mt * 16 + g;
                af[mt][0] = Ab[r * 36 + ks * 8 + tg];
                af[mt][1] = Ab[(r + 8) * 36 + ks * 8 + tg];
                af[mt][2] = Ab[r * 36 + ks * 8 + tg + 4];
                af[mt][3] = Ab[(r + 8) * 36 + ks * 8 + tg + 4];
            }
#pragma unroll
            for (int nt = 0; nt < 4; nt++) {
                int nl = wn * 32 + nt * 8 + g;
                bf[nt][0] = Bb[nl * 36 + ks * 8 + tg];
                bf[nt][1] = Bb[nl * 36 + ks * 8 + tg + 4];
            }
#pragma unroll
            for (int mt = 0; mt < 4; mt++)
#pragma unroll
                for (int nt = 0; nt < 4; nt++)
                    mma_tf32(acc[mt][nt], af[mt], bf[nt]);
        }
        buf ^= 1;
    }

#pragma unroll
    for (int mt = 0; mt < 4; mt++) {
        int r0 = bm + wm * 64 + mt * 16 + g;
#pragma unroll
        for (int nt = 0; nt < 4; nt++) {
            int c = bn + wn * 32 + nt * 8 + tg * 2;
            int s0 = (c & 3) * H + (c >> 2);
            int s1 = ((c + 1) & 3) * H + ((c + 1) >> 2);
            float bb0 = b1[s0] + b2[s0];
            float bb1 = b1[s1] + b2[s1];
            C[(size_t)r0 * N + c]           = acc[mt][nt][0] + bb0;
            C[(size_t)r0 * N + c + 1]       = acc[mt][nt][1] + bb1;
            C[(size_t)(r0 + 8) * N + c]     = acc[mt][nt][2] + bb0;
            C[(size_t)(r0 + 8) * N + c + 1] = acc[mt][nt][3] + bb1;
        }
    }
}

// ---------------- cluster LSTM recurrence with st.async + mbarrier sync ----------------
// Same decomposition as Round 6 (8 batch-groups x 8-CTA clusters, JPC units/rank,
// weights in registers), but no cluster.sync in the loop:
//  - full[2] mbarriers (count 1, tx = 32*HD bytes): h(t) delivery via st.async.
//  - empty[2] mbarriers (count 8): read-completion backpressure; thread0
//    remote-arrives all 8 after the MMA has consumed buffer rb.
// Max skew between CTAs is 1 step; early complete_tx before expect_tx is safe
// (signed tx-count balances at the expect).
template <int HD, int JPC, int NT, bool STORE_OUT>
__global__ void __launch_bounds__(NT, 1) __cluster_dims__(8, 1, 1)
lstm_recur_mb(const float* __restrict__ xg,    // [b][t][j*4+g]
              const float* __restrict__ Whh,   // [4*HD][HD]
              float* __restrict__ out,         // [b][t][HD] (layer1) or null
              float* __restrict__ hfin,        // [64][HD] final h (layer2) or null
              int T)
{
    constexpr int KS  = HD / 8;          // mma k-steps
    constexpr int HDP = HD + 4;          // padded h row stride (words)
    constexpr int RP  = 4 * JPC + 4;     // padded partial row stride
    constexpr unsigned FBYTES = 32u * HD;  // 8 batches * HD units * 4 B per phase

    extern __shared__ unsigned smem_u[];
    // [0:8)  4 mbarriers (u64): full0, full1, empty0, empty1
    unsigned* hs = smem_u + 8;                   // [2][8][HDP] tf32 h
    float* part  = (float*)(hs + 2 * 8 * HDP);   // [8][RP]

    const int tid = threadIdx.x, lane = tid & 31, warp = tid >> 5;
    const int g = lane >> 2, tg = lane & 3;
    const uint32_t rank = my_ctarank();
    const int bg = blockIdx.x >> 3;
    const int jbase = (int)rank * JPC;
    const int bglob0 = bg * 8;

    const uint32_t mbb = smem_u32(smem_u);
    const uint32_t FULL0 = mbb, FULL1 = mbb + 8u, EMPT0 = mbb + 16u, EMPT1 = mbb + 24u;

    // ---- preload weight fragments into registers (once) ----
    unsigned areg[KS][4];
    {
        int lr0 = warp * 16 + g, lr1 = lr0 + 8;
        const float* w0 = Whh + (size_t)((lr0 & 3) * HD + jbase + (lr0 >> 2)) * HD;
        const float* w1 = Whh + (size_t)((lr1 & 3) * HD + jbase + (lr1 >> 2)) * HD;
#pragma unroll
        for (int ks = 0; ks < KS; ks++) {
            areg[ks][0] = f2tf32(w0[ks * 8 + tg]);
            areg[ks][1] = f2tf32(w1[ks * 8 + tg]);
            areg[ks][2] = f2tf32(w0[ks * 8 + tg + 4]);
            areg[ks][3] = f2tf32(w1[ks * 8 + tg + 4]);
        }
    }

    // zero both h buffers; init barriers; pre-arm full[1] (first write target)
    for (int i = tid; i < 2 * 8 * HDP; i += NT) hs[i] = 0u;
    if (tid == 0) {
        mbar_init(FULL0, 1); mbar_init(FULL1, 1);
        mbar_init(EMPT0, 8); mbar_init(EMPT1, 8);
        mbar_expect_tx(FULL1, FBYTES);
    }
    __syncthreads();
    CLUSTER_ARRIVE();
    CLUSTER_WAIT();

    // updater mapping: one (batch, unit) per thread (NT == 8*JPC)
    const int b  = tid / JPC;
    const int jl = tid % JPC;
    const float* xgp = xg + ((size_t)(bglob0 + b) * T) * (4 * HD) + (jbase + jl) * 4;
    const uint32_t hs_base = smem_u32(hs);
    float cc = 0.f;
    float4 xv = *(const float4*)xgp;   // step 0 gates
    unsigned phf0 = 0, phf1 = 0, phe0 = 0, phe1 = 0;

    for (int t = 0; t < T; t++) {
        const int rb = t & 1, wb = rb ^ 1;

        // wait for h(t-1) delivery (skip t=0: zeros staged locally)
        if (t > 0) {
            if (rb) { mbar_wait(FULL1, phf1); phf1 ^= 1; }
            else    { mbar_wait(FULL0, phf0); phf0 ^= 1; }
        }

        // ---- mma: rows [warp*16,+16) x 8 batches, 4 accumulator chains ----
        {
            float acc[4][4];
#pragma unroll
            for (int ch = 0; ch < 4; ch++)
#pragma unroll
                for (int i = 0; i < 4; i++) acc[ch][i] = 0.f;

            const unsigned* hb = hs + rb * 8 * HDP + g * HDP;  // batch g
#pragma unroll
            for (int ks = 0; ks < KS; ks++) {
                unsigned bf[2];
                bf[0] = hb[ks * 8 + tg];
                bf[1] = hb[ks * 8 + tg + 4];
                mma_tf32(acc[ks & 3], areg[ks], bf);
            }
            float s0 = (acc[0][0] + acc[1][0]) + (acc[2][0] + acc[3][0]);
            float s1 = (acc[0][1] + acc[1][1]) + (acc[2][1] + acc[3][1]);
            float s2 = (acc[0][2] + acc[1][2]) + (acc[2][2] + acc[3][2]);
            float s3 = (acc[0][3] + acc[1][3]) + (acc[2][3] + acc[3][3]);
            int lr = warp * 16 + g;
            part[(tg * 2 + 0) * RP + lr]     = s0;
            part[(tg * 2 + 1) * RP + lr]     = s1;
            part[(tg * 2 + 0) * RP + lr + 8] = s2;
            part[(tg * 2 + 1) * RP + lr + 8] = s3;
        }
        __syncthreads();   // h reads + partials done

        // arm full[rb] for its next use, and release read-lock on rb to all CTAs
        if (tid == 0) {
            mbar_expect_tx(rb ? FULL1 : FULL0, FBYTES);
            uint32_t eb = rb ? EMPT1 : EMPT0;
#pragma unroll
            for (int r = 0; r < 8; r++) mbar_arrive_remote(eb, r);
        }

        // ---- update one (batch, unit) ----
        float4 p = *(const float4*)(part + b * RP + jl * 4);  // gates i,f,c,o
        float iv = fsigmoid(p.x + xv.x);
        float fv = fsigmoid(p.y + xv.y);
        float gv = ftanh(p.z + xv.z);
        float ov = fsigmoid(p.w + xv.w);
        cc = fv * cc + iv * gv;
        float hval = ov * ftanh(cc);
        unsigned hbits = f2tf32(hval);

        // backpressure: buffer wb must be fully consumed cluster-wide (skip t=0)
        if (t > 0) {
            if (wb) { mbar_wait(EMPT1, phe1); phe1 ^= 1; }
            else    { mbar_wait(EMPT0, phe0); phe0 ^= 1; }
        }

        // publish h to all 8 CTAs (incl self) with tx credit on their full[wb]
        {
            uint32_t loff = hs_base + 4u * (uint32_t)((wb * 8 + b) * HDP + jbase + jl);
            uint32_t fb = wb ? FULL1 : FULL0;
#pragma unroll
            for (int r = 0; r < 8; r++) st_async_b32(loff, hbits, fb, r);
        }

        if (STORE_OUT)
            out[((size_t)(bglob0 + b) * T + t) * HD + jbase + jl] = __uint_as_float(hbits);
        if (hfin && t == T - 1)
            hfin[(size_t)(bglob0 + b) * HD + jbase + jl] = __uint_as_float(hbits);

        // prefetch next step's gates (hides DRAM latency behind peers' writes)
        if (t + 1 < T)
            xv = *(const float4*)(xgp + (size_t)(t + 1) * (4 * HD));
    }

    // drain: consume the final delivery into buffer 0 (T even), then cluster sync
    mbar_wait(FULL0, phf0);
    CLUSTER_ARRIVE();
    CLUSTER_WAIT();
}

// ---------------- FC head (parallel): 64 blocks x 64 threads ----------------
__global__ void __launch_bounds__(64) fc_head_par(
    const float* __restrict__ h2,     // [64][128]
    const float* __restrict__ Wfc,    // [64][128]
    const float* __restrict__ bfc,    // [64]
    const float* __restrict__ Wout,   // [1][64]
    const float* __restrict__ bout,   // [1]
    float* __restrict__ outp)         // [64]
{
    __shared__ float hrs[128];
    __shared__ float red[64];
    const int b = blockIdx.x, u = threadIdx.x;

    ((float2*)hrs)[u] = ((const float2*)(h2 + b * 128))[u];
    __syncthreads();

    const float4* wr = (const float4*)(Wfc + u * 128);
    float s0 = 0.f, s1 = 0.f, s2 = 0.f, s3 = 0.f;
#pragma unroll
    for (int k = 0; k < 32; k += 4) {
        float4 w0 = wr[k],     w1 = wr[k + 1], w2 = wr[k + 2], w3 = wr[k + 3];
        const float* h0 = hrs + k * 4;
        s0 += w0.x * h0[0]  + w0.y * h0[1]  + w0.z * h0[2]  + w0.w * h0[3];
        s1 += w1.x * h0[4]  + w1.y * h0[5]  + w1.z * h0[6]  + w1.w * h0[7];
        s2 += w2.x * h0[8]  + w2.y * h0[9]  + w2.z * h0[10] + w2.w * h0[11];
        s3 += w3.x * h0[12] + w3.y * h0[13] + w3.z * h0[14] + w3.w * h0[15];
    }
    float s = (s0 + s1) + (s2 + s3) + bfc[u];
    red[u] = fmaxf(s, 0.f) * Wout[u];
    __syncthreads();

    if (u < 32) {
        float v = red[u] + red[u + 32];
#pragma unroll
        for (int off = 16; off > 0; off >>= 1)
            v += __shfl_down_sync(0xffffffffu, v, off);
        if (u == 0) outp[b] = v + bout[0];
    }
}

// ---------------- launch ----------------
extern "C" void kernel_launch(void* const* d_in, const int* in_sizes, int n_in,
                              void* d_out, int out_size)
{
    const float* x    = (const float*)d_in[0];
    const float* Wih1 = (const float*)d_in[1];
    const float* Whh1 = (const float*)d_in[2];
    const float* bih1 = (const float*)d_in[3];
    const float* bhh1 = (const float*)d_in[4];
    const float* Wih2 = (const float*)d_in[5];
    const float* Whh2 = (const float*)d_in[6];
    const float* bih2 = (const float*)d_in[7];
    const float* bhh2 = (const float*)d_in[8];
    const float* Wfc1 = (const float*)d_in[9];
    const float* bfc1 = (const float*)d_in[10];
    const float* Wout = (const float*)d_in[11];
    const float* bout = (const float*)d_in[12];
    float* outp = (float*)d_out;

    float *xg1, *out1, *xg2, *w1cv, *w2cv, *h2f;
    cudaGetSymbolAddress((void**)&xg1,  g_xg1);
    cudaGetSymbolAddress((void**)&out1, g_out1);
    cudaGetSymbolAddress((void**)&xg2,  g_xg2);
    cudaGetSymbolAddress((void**)&w1cv, g_w1cv);
    cudaGetSymbolAddress((void**)&w2cv, g_w2cv);
    cudaGetSymbolAddress((void**)&h2f,  g_h2f);

    const int GEMM_SMEM = 2 * 128 * 36 * 4 * 2;                      // 73728 B
    const int R1_SMEM = 32 + (2 * 8 * 260) * 4 + 8 * 132 * 4;        // 20896 B
    const int R2_SMEM = 32 + (2 * 8 * 132) * 4 + 8 * 68 * 4;         // 10656 B
    cudaFuncSetAttribute(gemm_tf32_perm,
                         cudaFuncAttributeMaxDynamicSharedMemorySize, GEMM_SMEM);
    cudaFuncSetAttribute(lstm_recur_mb<256, 32, 256, true>,
                         cudaFuncAttributeMaxDynamicSharedMemorySize, 64 * 1024);
    cudaFuncSetAttribute(lstm_recur_mb<128, 16, 128, false>,
                         cudaFuncAttributeMaxDynamicSharedMemorySize, 64 * 1024);

    // prep: round input-projection weights to tf32
    cvt_rna_kernel<<<(1024 * 2048 + 255) / 256, 256>>>(Wih1, w1cv, 1024 * 2048);
    cvt_rna_kernel<<<(512 * 256 + 255) / 256, 256>>>(Wih2, w2cv, 512 * 256);

    const int M = 64 * 512;

    // layer 1 input projection
    gemm_tf32_perm<<<dim3(1024 / 128, M / 128), 256, GEMM_SMEM>>>(
        x, w1cv, bih1, bhh1, xg1, M, 1024, 2048);

    // layer 1 recurrence: 8 batch-groups x 8-CTA clusters
    lstm_recur_mb<256, 32, 256, true><<<64, 256, R1_SMEM>>>(
        xg1, Whh1, out1, (float*)0, 512);

    // layer 2 input projection
    gemm_tf32_perm<<<dim3(512 / 128, M / 128), 256, GEMM_SMEM>>>(
        out1, w2cv, bih2, bhh2, xg2, M, 512, 256);

    // layer 2 recurrence
    lstm_recur_mb<128, 16, 128, false><<<64, 128, R2_SMEM>>>(
        xg2, Whh2, (float*)0, h2f, 512);

    // FC head (parallel)
    fc_head_par<<<64, 64>>>(h2f, Wfc1, bfc1, Wout, bout, outp);
}

// round 11
// speedup vs baseline: 2.0809x; 1.2926x over previous
#include <cuda_runtime.h>
#include <cuda_fp16.h>
#include <math.h>
#include <stdint.h>

// ---------------- static device scratch (no allocation allowed) ----------------
__device__ __half  g_xh  [(size_t)32768 * 2048];   // x converted to fp16 (128 MB)
__device__ float   g_xg1 [(size_t)32768 * 1024];   // layer1 gates, layout [b][t][j*4+g] (fp32)
__device__ __half  g_out1[(size_t)32768 * 256];    // layer1 hidden outputs [b][t][j] (fp16)
__device__ float   g_xg2 [(size_t)32768 * 512];    // layer2 gates [b][t][j*4+g] (fp32)
__device__ __half  g_w1h [(size_t)1024 * 2048];    // Wih1 fp16
__device__ __half  g_w2h [(size_t)512 * 256];      // Wih2 fp16
__device__ float   g_h2f [64 * 128];               // final layer2 h (fp32)

// ---------------- helpers ----------------
__device__ __forceinline__ void mma_f16(float* c, const unsigned* a, const unsigned* b) {
    asm volatile(
        "mma.sync.aligned.m16n8k16.row.col.f32.f16.f16.f32 "
        "{%0,%1,%2,%3},{%4,%5,%6,%7},{%8,%9},{%0,%1,%2,%3};"
        : "+f"(c[0]), "+f"(c[1]), "+f"(c[2]), "+f"(c[3])
        : "r"(a[0]), "r"(a[1]), "r"(a[2]), "r"(a[3]), "r"(b[0]), "r"(b[1]));
}

__device__ __forceinline__ void cp_async16(void* smem_dst, const void* gptr) {
    unsigned s = (unsigned)__cvta_generic_to_shared(smem_dst);
    asm volatile("cp.async.cg.shared.global [%0], [%1], 16;\n" :: "r"(s), "l"(gptr));
}
#define CP_COMMIT() asm volatile("cp.async.commit_group;\n" ::: "memory")
#define CP_WAIT0()  asm volatile("cp.async.wait_group 0;\n" ::: "memory")

__device__ __forceinline__ uint32_t smem_u32(const void* p) {
    return (uint32_t)__cvta_generic_to_shared(p);
}
__device__ __forceinline__ uint32_t my_ctarank() {
    uint32_t r;
    asm("mov.u32 %0, %%cluster_ctarank;" : "=r"(r));
    return r;
}
#define CLUSTER_ARRIVE() asm volatile("barrier.cluster.arrive.aligned;" ::: "memory")
#define CLUSTER_WAIT()   asm volatile("barrier.cluster.wait.aligned;" ::: "memory")

__device__ __forceinline__ void mbar_init(uint32_t a, unsigned cnt) {
    asm volatile("mbarrier.init.shared.b64 [%0], %1;" :: "r"(a), "r"(cnt) : "memory");
}
__device__ __forceinline__ void mbar_expect_tx(uint32_t a, unsigned tx) {
    asm volatile("mbarrier.arrive.expect_tx.shared.b64 _, [%0], %1;"
                 :: "r"(a), "r"(tx) : "memory");
}
__device__ __forceinline__ void mbar_wait(uint32_t a, unsigned parity) {
    asm volatile(
        "{\n\t"
        ".reg .pred P1;\n\t"
        "WAIT_LOOP_%=:\n\t"
        "mbarrier.try_wait.parity.acquire.cta.shared::cta.b64 P1, [%0], %1, 0x989680;\n\t"
        "@P1 bra.uni WAIT_DONE_%=;\n\t"
        "bra.uni WAIT_LOOP_%=;\n\t"
        "WAIT_DONE_%=:\n\t"
        "}"
        :: "r"(a), "r"(parity) : "memory");
}
__device__ __forceinline__ void mbar_arrive_remote(uint32_t local_addr, int rank) {
    uint32_t ra;
    asm("mapa.shared::cluster.u32 %0, %1, %2;" : "=r"(ra) : "r"(local_addr), "r"(rank));
    asm volatile("mbarrier.arrive.shared::cluster.b64 _, [%0];" :: "r"(ra) : "memory");
}
__device__ __forceinline__ void st_async_b32(uint32_t local_dst, unsigned val,
                                             uint32_t local_mbar, int rank) {
    uint32_t ra, rm;
    asm("mapa.shared::cluster.u32 %0, %1, %2;" : "=r"(ra) : "r"(local_dst), "r"(rank));
    asm("mapa.shared::cluster.u32 %0, %1, %2;" : "=r"(rm) : "r"(local_mbar), "r"(rank));
    asm volatile("st.async.shared::cluster.mbarrier::complete_tx::bytes.b32 [%0], %1, [%2];"
                 :: "r"(ra), "r"(val), "r"(rm) : "memory");
}

// fast precise activations (MUFU ex2 + rcp; err ~1e-6)
__device__ __forceinline__ float fsigmoid(float x) {
    return 1.f / (1.f + __expf(-x));
}
__device__ __forceinline__ float ftanh(float x) {
    return 1.f - 2.f / (1.f + __expf(2.f * x));
}

// ---------------- prep: convert fp32 -> fp16 ----------------
__global__ void cvt_f16_kernel(const float* __restrict__ src, __half* __restrict__ dst, int n) {
    int i = (blockIdx.x * 256 + threadIdx.x) * 4;
    if (i < n) {
        float4 v = *(const float4*)(src + i);
        *(__half2*)(dst + i)     = __floats2half2_rn(v.x, v.y);
        *(__half2*)(dst + i + 2) = __floats2half2_rn(v.z, v.w);
    }
}

// ---------------- fp16 GEMM with permuted output columns ----------------
// C[m][n'] = sum_k A[m][k]*W[srcrow(n')][k] + b1[srcrow]+b2[srcrow], n'=j*4+g -> g*H+j.
// Tiles: 128M x 128N x 64K, 256 threads, 8 warps (2m x 4n, warp tile 64x32),
// double-buffered cp.async, m16n8k16 fp16 mma (fp32 accum).
// smem word layout identical to the old tf32 version: word = half2 (2 k-elems).
__global__ void __launch_bounds__(256, 2) gemm_f16_perm(
    const __half* __restrict__ A, const __half* __restrict__ W,
    const float* __restrict__ b1, const float* __restrict__ b2,
    float* __restrict__ C, int M, int N, int K)
{
    extern __shared__ unsigned sh[];
    unsigned* As = sh;                 // [2][128][36] (words of half2, 32 used)
    unsigned* Bs = sh + 2 * 128 * 36;  // [2][128][36]

    const int tid = threadIdx.x, lane = tid & 31, warp = tid >> 5;
    const int wm = warp & 1, wn = warp >> 1;
    const int g = lane >> 2, tg = lane & 3;
    const int bn = blockIdx.x * 128, bm = blockIdx.y * 128;
    const int H = N >> 2;

    float acc[4][4][4];
#pragma unroll
    for (int a = 0; a < 4; a++)
#pragma unroll
        for (int b = 0; b < 4; b++)
#pragma unroll
            for (int c = 0; c < 4; c++) acc[a][b][c] = 0.f;

    const int NK = K >> 6;    // 64 k per tile

    // prologue: tile 0 (A/B each: 128 rows x 8 float4)
#pragma unroll
    for (int i = 0; i < 4; i++) {
        int id = tid + i * 256, row = id >> 3, c4 = id & 7;
        cp_async16(&As[row * 36 + c4 * 4], A + (size_t)(bm + row) * K + c4 * 8);
        int np = bn + row;
        int srow = (np & 3) * H + (np >> 2);
        cp_async16(&Bs[row * 36 + c4 * 4], W + (size_t)srow * K + c4 * 8);
    }
    CP_COMMIT();

    int buf = 0;
    for (int kt = 0; kt < NK; kt++) {
        CP_WAIT0();
        __syncthreads();
        if (kt + 1 < NK) {
            int koff = (kt + 1) * 64;
            int nb = buf ^ 1;
#pragma unroll
            for (int i = 0; i < 4; i++) {
                int id = tid + i * 256, row = id >> 3, c4 = id & 7;
                cp_async16(&As[nb * 128 * 36 + row * 36 + c4 * 4],
                           A + (size_t)(bm + row) * K + koff + c4 * 8);
                int np = bn + row;
                int srow = (np & 3) * H + (np >> 2);
                cp_async16(&Bs[nb * 128 * 36 + row * 36 + c4 * 4],
                           W + (size_t)srow * K + koff + c4 * 8);
            }
        }
        CP_COMMIT();

        const unsigned* Ab = As + buf * 128 * 36;
        const unsigned* Bb = Bs + buf * 128 * 36;
#pragma unroll
        for (int ks = 0; ks < 4; ks++) {   // 4 x k=16 slices
            unsigned af[4][4], bf[4][2];
#pragma unroll
            for (int mt = 0; mt < 4; mt++) {
                int r = wm * 64 + mt * 16 + g;
                af[mt][0] = Ab[r * 36 + ks * 8 + tg];
                af[mt][1] = Ab[(r + 8) * 36 + ks * 8 + tg];
                af[mt][2] = Ab[r * 36 + ks * 8 + tg + 4];
                af[mt][3] = Ab[(r + 8) * 36 + ks * 8 + tg + 4];
            }
#pragma unroll
            for (int nt = 0; nt < 4; nt++) {
                int nl = wn * 32 + nt * 8 + g;
                bf[nt][0] = Bb[nl * 36 + ks * 8 + tg];
                bf[nt][1] = Bb[nl * 36 + ks * 8 + tg + 4];
            }
#pragma unroll
            for (int mt = 0; mt < 4; mt++)
#pragma unroll
                for (int nt = 0; nt < 4; nt++)
                    mma_f16(acc[mt][nt], af[mt], bf[nt]);
        }
        buf ^= 1;
    }

    // epilogue: permuted bias + fp32 store (C frag layout same as tf32 case)
#pragma unroll
    for (int mt = 0; mt < 4; mt++) {
        int r0 = bm + wm * 64 + mt * 16 + g;
#pragma unroll
        for (int nt = 0; nt < 4; nt++) {
            int c = bn + wn * 32 + nt * 8 + tg * 2;
            int s0 = (c & 3) * H + (c >> 2);
            int s1 = ((c + 1) & 3) * H + ((c + 1) >> 2);
            float bb0 = b1[s0] + b2[s0];
            float bb1 = b1[s1] + b2[s1];
            C[(size_t)r0 * N + c]           = acc[mt][nt][0] + bb0;
            C[(size_t)r0 * N + c + 1]       = acc[mt][nt][1] + bb1;
            C[(size_t)(r0 + 8) * N + c]     = acc[mt][nt][2] + bb0;
            C[(size_t)(r0 + 8) * N + c + 1] = acc[mt][nt][3] + bb1;
        }
    }
}

// ---------------- cluster LSTM recurrence, fp16 MMA + st.async/mbarrier ----------------
// 8 batch-groups x 8-CTA clusters; rank owns JPC units (4*JPC gate rows, 16/warp).
// h kept as half2 words in SMEM; weights as packed half2 fragments in registers.
// Per step: m16n8k16 MMA (K=HD) -> partials -> gate update -> paired st.async
// broadcast (even-jl threads store half2 words) -> mbarrier tx completion.
template <int HD, int JPC, int NT, bool STORE_OUT>
__global__ void __launch_bounds__(NT, 1) __cluster_dims__(8, 1, 1)
lstm_recur_f16(const float* __restrict__ xg,    // [b][t][j*4+g] fp32
               const float* __restrict__ Whh,   // [4*HD][HD] fp32
               __half* __restrict__ out,        // [b][t][HD] fp16 (layer1) or null
               float* __restrict__ hfin,        // [64][HD] fp32 (layer2) or null
               int T)
{
    constexpr int KS = HD / 16;            // mma k-steps
    constexpr int HW = HD / 2 + 4;         // padded half2-words per batch row
    constexpr int RP = 4 * JPC + 4;        // padded partial row stride
    constexpr unsigned FBYTES = 16u * HD;  // 8 batches * HD * 2 B per phase

    extern __shared__ unsigned smem_u[];
    unsigned* hs = smem_u + 8;                   // [2][8][HW] half2 words
    float* part  = (float*)(hs + 2 * 8 * HW);    // [8][RP]

    const int tid = threadIdx.x, lane = tid & 31, warp = tid >> 5;
    const int g = lane >> 2, tg = lane & 3;
    const uint32_t rank = my_ctarank();
    const int bg = blockIdx.x >> 3;
    const int jbase = (int)rank * JPC;
    const int bglob0 = bg * 8;

    const uint32_t mbb = smem_u32(smem_u);
    const uint32_t FULL0 = mbb, FULL1 = mbb + 8u, EMPT0 = mbb + 16u, EMPT1 = mbb + 24u;

    // ---- preload packed fp16 weight fragments (once) ----
    unsigned areg[KS][4];
    {
        int lr0 = warp * 16 + g, lr1 = lr0 + 8;
        const float* w0 = Whh + (size_t)((lr0 & 3) * HD + jbase + (lr0 >> 2)) * HD;
        const float* w1 = Whh + (size_t)((lr1 & 3) * HD + jbase + (lr1 >> 2)) * HD;
#pragma unroll
        for (int ks = 0; ks < KS; ks++) {
            __half2 p0 = __floats2half2_rn(w0[ks * 16 + tg * 2],     w0[ks * 16 + tg * 2 + 1]);
            __half2 p1 = __floats2half2_rn(w1[ks * 16 + tg * 2],     w1[ks * 16 + tg * 2 + 1]);
            __half2 p2 = __floats2half2_rn(w0[ks * 16 + 8 + tg * 2], w0[ks * 16 + 8 + tg * 2 + 1]);
            __half2 p3 = __floats2half2_rn(w1[ks * 16 + 8 + tg * 2], w1[ks * 16 + 8 + tg * 2 + 1]);
            areg[ks][0] = *(unsigned*)&p0;
            areg[ks][1] = *(unsigned*)&p1;
            areg[ks][2] = *(unsigned*)&p2;
            areg[ks][3] = *(unsigned*)&p3;
        }
    }

    for (int i = tid; i < 2 * 8 * HW; i += NT) hs[i] = 0u;
    if (tid == 0) {
        mbar_init(FULL0, 1); mbar_init(FULL1, 1);
        mbar_init(EMPT0, 8); mbar_init(EMPT1, 8);
        mbar_expect_tx(FULL1, FBYTES);
    }
    __syncthreads();
    CLUSTER_ARRIVE();
    CLUSTER_WAIT();

    const int b  = tid / JPC;
    const int jl = tid % JPC;
    const float* xgp = xg + ((size_t)(bglob0 + b) * T) * (4 * HD) + (jbase + jl) * 4;
    const uint32_t hs_base = smem_u32(hs);
    float cc = 0.f;
    float4 xv = *(const float4*)xgp;
    unsigned phf0 = 0, phf1 = 0, phe0 = 0, phe1 = 0;

    for (int t = 0; t < T; t++) {
        const int rb = t & 1, wb = rb ^ 1;

        if (t > 0) {
            if (rb) { mbar_wait(FULL1, phf1); phf1 ^= 1; }
            else    { mbar_wait(FULL0, phf0); phf0 ^= 1; }
        }

        // ---- mma: rows [warp*16,+16) x 8 batches, k = HD (fp16, k16 steps) ----
        {
            float acc[4][4];
#pragma unroll
            for (int ch = 0; ch < 4; ch++)
#pragma unroll
                for (int i = 0; i < 4; i++) acc[ch][i] = 0.f;

            const unsigned* hb = hs + rb * 8 * HW + g * HW;   // batch g
#pragma unroll
            for (int ks = 0; ks < KS; ks++) {
                unsigned bf[2];
                bf[0] = hb[ks * 8 + tg];
                bf[1] = hb[ks * 8 + tg + 4];
                mma_f16(acc[ks & 3], areg[ks], bf);
            }
            float s0 = (acc[0][0] + acc[1][0]) + (acc[2][0] + acc[3][0]);
            float s1 = (acc[0][1] + acc[1][1]) + (acc[2][1] + acc[3][1]);
            float s2 = (acc[0][2] + acc[1][2]) + (acc[2][2] + acc[3][2]);
            float s3 = (acc[0][3] + acc[1][3]) + (acc[2][3] + acc[3][3]);
            int lr = warp * 16 + g;
            part[(tg * 2 + 0) * RP + lr]     = s0;
            part[(tg * 2 + 1) * RP + lr]     = s1;
            part[(tg * 2 + 0) * RP + lr + 8] = s2;
            part[(tg * 2 + 1) * RP + lr + 8] = s3;
        }
        __syncthreads();

        if (tid == 0) {
            mbar_expect_tx(rb ? FULL1 : FULL0, FBYTES);
            uint32_t eb = rb ? EMPT1 : EMPT0;
#pragma unroll
            for (int r = 0; r < 8; r++) mbar_arrive_remote(eb, r);
        }

        // ---- update one (batch, unit) ----
        float4 p = *(const float4*)(part + b * RP + jl * 4);
        float iv = fsigmoid(p.x + xv.x);
        float fv = fsigmoid(p.y + xv.y);
        float gv = ftanh(p.z + xv.z);
        float ov = fsigmoid(p.w + xv.w);
        cc = fv * cc + iv * gv;
        float hval = ov * ftanh(cc);

        // pair with neighbor unit (jl^1 is the adjacent lane)
        float nbh = __shfl_xor_sync(0xffffffffu, hval, 1);

        if (t > 0) {
            if (wb) { mbar_wait(EMPT1, phe1); phe1 ^= 1; }
            else    { mbar_wait(EMPT0, phe0); phe0 ^= 1; }
        }

        if ((jl & 1) == 0) {
            __half2 h2 = __floats2half2_rn(hval, nbh);    // low = even unit
            unsigned hbits = *(unsigned*)&h2;
            uint32_t loff = hs_base +
                4u * (uint32_t)((wb * 8 + b) * HW + ((jbase + jl) >> 1));
            uint32_t fb = wb ? FULL1 : FULL0;
#pragma unroll
            for (int r = 0; r < 8; r++) st_async_b32(loff, hbits, fb, r);
            if (STORE_OUT)
                *(__half2*)(out + ((size_t)(bglob0 + b) * T + t) * HD + jbase + jl) = h2;
        }
        if (hfin && t == T - 1)
            hfin[(size_t)(bglob0 + b) * HD + jbase + jl] = hval;

        if (t + 1 < T)
            xv = *(const float4*)(xgp + (size_t)(t + 1) * (4 * HD));
    }

    mbar_wait(FULL0, phf0);
    CLUSTER_ARRIVE();
    CLUSTER_WAIT();
}

// ---------------- FC head (parallel): 64 blocks x 64 threads ----------------
__global__ void __launch_bounds__(64) fc_head_par(
    const float* __restrict__ h2,     // [64][128]
    const float* __restrict__ Wfc,    // [64][128]
    const float* __restrict__ bfc,    // [64]
    const float* __restrict__ Wout,   // [1][64]
    const float* __restrict__ bout,   // [1]
    float* __restrict__ outp)         // [64]
{
    __shared__ float hrs[128];
    __shared__ float red[64];
    const int b = blockIdx.x, u = threadIdx.x;

    ((float2*)hrs)[u] = ((const float2*)(h2 + b * 128))[u];
    __syncthreads();

    const float4* wr = (const float4*)(Wfc + u * 128);
    float s0 = 0.f, s1 = 0.f, s2 = 0.f, s3 = 0.f;
#pragma unroll
    for (int k = 0; k < 32; k += 4) {
        float4 w0 = wr[k],     w1 = wr[k + 1], w2 = wr[k + 2], w3 = wr[k + 3];
        const float* h0 = hrs + k * 4;
        s0 += w0.x * h0[0]  + w0.y * h0[1]  + w0.z * h0[2]  + w0.w * h0[3];
        s1 += w1.x * h0[4]  + w1.y * h0[5]  + w1.z * h0[6]  + w1.w * h0[7];
        s2 += w2.x * h0[8]  + w2.y * h0[9]  + w2.z * h0[10] + w2.w * h0[11];
        s3 += w3.x * h0[12] + w3.y * h0[13] + w3.z * h0[14] + w3.w * h0[15];
    }
    float s = (s0 + s1) + (s2 + s3) + bfc[u];
    red[u] = fmaxf(s, 0.f) * Wout[u];
    __syncthreads();

    if (u < 32) {
        float v = red[u] + red[u + 32];
#pragma unroll
        for (int off = 16; off > 0; off >>= 1)
            v += __shfl_down_sync(0xffffffffu, v, off);
        if (u == 0) outp[b] = v + bout[0];
    }
}

// ---------------- launch ----------------
extern "C" void kernel_launch(void* const* d_in, const int* in_sizes, int n_in,
                              void* d_out, int out_size)
{
    const float* x    = (const float*)d_in[0];
    const float* Wih1 = (const float*)d_in[1];
    const float* Whh1 = (const float*)d_in[2];
    const float* bih1 = (const float*)d_in[3];
    const float* bhh1 = (const float*)d_in[4];
    const float* Wih2 = (const float*)d_in[5];
    const float* Whh2 = (const float*)d_in[6];
    const float* bih2 = (const float*)d_in[7];
    const float* bhh2 = (const float*)d_in[8];
    const float* Wfc1 = (const float*)d_in[9];
    const float* bfc1 = (const float*)d_in[10];
    const float* Wout = (const float*)d_in[11];
    const float* bout = (const float*)d_in[12];
    float* outp = (float*)d_out;

    __half *xh, *out1h, *w1h, *w2h;
    float *xg1, *xg2, *h2f;
    cudaGetSymbolAddress((void**)&xh,    g_xh);
    cudaGetSymbolAddress((void**)&xg1,   g_xg1);
    cudaGetSymbolAddress((void**)&out1h, g_out1);
    cudaGetSymbolAddress((void**)&xg2,   g_xg2);
    cudaGetSymbolAddress((void**)&w1h,   g_w1h);
    cudaGetSymbolAddress((void**)&w2h,   g_w2h);
    cudaGetSymbolAddress((void**)&h2f,   g_h2f);

    const int GEMM_SMEM = 2 * 128 * 36 * 4 * 2;                    // 73728 B
    const int R1_SMEM = 32 + (2 * 8 * 132) * 4 + 8 * 132 * 4;      // 12704 B
    const int R2_SMEM = 32 + (2 * 8 * 68) * 4 + 8 * 68 * 4;        // 6560 B
    cudaFuncSetAttribute(gemm_f16_perm,
                         cudaFuncAttributeMaxDynamicSharedMemorySize, GEMM_SMEM);
    cudaFuncSetAttribute(lstm_recur_f16<256, 32, 256, true>,
                         cudaFuncAttributeMaxDynamicSharedMemorySize, 64 * 1024);
    cudaFuncSetAttribute(lstm_recur_f16<128, 16, 128, false>,
                         cudaFuncAttributeMaxDynamicSharedMemorySize, 64 * 1024);

    // prep: fp16 conversions
    cvt_f16_kernel<<<(32768 * 2048 / 4 + 255) / 256, 256>>>(x, xh, 32768 * 2048);
    cvt_f16_kernel<<<(1024 * 2048 / 4 + 255) / 256, 256>>>(Wih1, w1h, 1024 * 2048);
    cvt_f16_kernel<<<(512 * 256 / 4 + 255) / 256, 256>>>(Wih2, w2h, 512 * 256);

    const int M = 64 * 512;

    // layer 1 input projection (fp16 mma)
    gemm_f16_perm<<<dim3(1024 / 128, M / 128), 256, GEMM_SMEM>>>(
        xh, w1h, bih1, bhh1, xg1, M, 1024, 2048);

    // layer 1 recurrence
    lstm_recur_f16<256, 32, 256, true><<<64, 256, R1_SMEM>>>(
        xg1, Whh1, out1h, (float*)0, 512);

    // layer 2 input projection (A = fp16 out1)
    gemm_f16_perm<<<dim3(512 / 128, M / 128), 256, GEMM_SMEM>>>(
        out1h, w2h, bih2, bhh2, xg2, M, 512, 256);

    // layer 2 recurrence
    lstm_recur_f16<128, 16, 128, false><<<64, 128, R2_SMEM>>>(
        xg2, Whh2, (__half*)0, h2f, 512);

    // FC head (parallel)
    fc_head_par<<<64, 64>>>(h2f, Wfc1, bfc1, Wout, bout, outp);
}